// round 7
// baseline (speedup 1.0000x reference)
#include <cuda_runtime.h>
#include <cuda_bf16.h>

// PointMatcher: pred (N=1024,20,2) vs gt (M=2048,20,2)
// dist(i,j) = mean_p ||pred[i,p]-gt[j,p]|| ; argmin over j per i.
// Outputs concatenated in d_out (float32):
//   [0..N*40) matched gt rows | [N*40..N*41) confidence | [N*41..N*42) indices

#define BI      2       // pred rows per block
#define TJ      256     // gt rows per tile
#define HJ      128     // thread handles rows jl and jl+HJ
#define P       20
#define ROWF    40      // floats per gt row
#define ROWP    42      // shared stride: 10*jl mod 32 distinct over 16 rows/warp
#define THREADS 256
#define TILEF   (TJ * ROWP)                 // 10752 floats = 43008 B
#define SMEM_BYTES (TILEF*4 + BI*8)

typedef unsigned long long ull;

__device__ __forceinline__ float fsqrt_approx(float x) {
    float r;
    asm("sqrt.approx.f32 %0, %1;" : "=f"(r) : "f"(x));
    return r;
}
// sqrt((gx-px)^2 + (gy-py)^2) with packed diff/square (pneg = {-px,-py})
__device__ __forceinline__ float pair_dist(ull g, ull pneg) {
    ull d, q;
    asm("add.rn.f32x2 %0, %1, %2;" : "=l"(d) : "l"(g), "l"(pneg));
    asm("mul.rn.f32x2 %0, %1, %2;" : "=l"(q) : "l"(d), "l"(d));
    float a, b;
    asm("mov.b64 {%0,%1}, %2;" : "=f"(a), "=f"(b) : "l"(q));
    return fsqrt_approx(a + b);
}

__global__ __launch_bounds__(THREADS, 4)
void pointmatcher_kernel(const float* __restrict__ pred,
                         const float* __restrict__ gt,
                         float* __restrict__ out_mp,
                         float* __restrict__ out_conf,
                         float* __restrict__ out_idx,
                         int N, int M)
{
    extern __shared__ float smem[];
    float* tile = smem;
    ull*   best = (ull*)(smem + TILEF);

    const int tid = threadIdx.x;
    const int il  = tid & (BI - 1);      // 0..1 : pred row within block
    const int jl  = tid >> 1;            // 0..127: gt rows jl, jl+HJ per tile
    const int i   = blockIdx.x * BI + il;

    if (tid < BI) best[tid] = ~0ull;     // visible after first __syncthreads

    // Negated pred row in registers, packed {-x,-y} per point (40 regs).
    ull pr[P];
    {
        const float2* p2 = (const float2*)(pred + (size_t)i * ROWF);
        #pragma unroll
        for (int p = 0; p < P; p++) {
            float2 v = p2[p];
            float nx = -v.x, ny = -v.y;
            asm("mov.b64 %0, {%1,%2};" : "=l"(pr[p]) : "f"(nx), "f"(ny));
        }
    }

    float minv = 3.402823466e+38f;       // min of SUM over P (mean deferred)
    int   minj = 0;

    for (int jt = 0; jt < M; jt += TJ) {
        __syncthreads();                 // previous tile fully consumed
        // Tile load: TJ*ROWF/2 = 5120 float2, 20 per thread, coalesced.
        const float2* src = (const float2*)(gt + (size_t)jt * ROWF);
        #pragma unroll
        for (int it = 0; it < 20; it++) {
            int f   = tid + it * THREADS;        // float2 index 0..5119
            int row = f / (ROWF / 2);
            int k2  = f - row * (ROWF / 2);
            *(float2*)(tile + row * ROWP + k2 * 2) = src[f];
        }
        __syncthreads();

        const ull* t0 = (const ull*)(tile + jl * ROWP);
        const ull* t1 = (const ull*)(tile + (jl + HJ) * ROWP);
        float sum0 = 0.f, sum1 = 0.f;
        #pragma unroll
        for (int p = 0; p < P; p++) {
            sum0 += pair_dist(t0[p], pr[p]);
            sum1 += pair_dist(t1[p], pr[p]);
        }
        int j0 = jt + jl;
        int j1 = jt + jl + HJ;
        if (sum0 < minv) { minv = sum0; minj = j0; }  // ascending j per thread:
        if (sum1 < minv) { minv = sum1; minj = j1; }  // '<' keeps first tie
    }

    // Block argmin: packed (dist_bits, j); min == (min dist, then min j).
    ull key = ((ull)__float_as_uint(minv) << 32) | (unsigned)minj;
    atomicMin(&best[il], key);
    __syncthreads();

    if (tid < BI) {
        ull b = best[tid];
        int j = (int)(unsigned)b;
        float md = __uint_as_float((unsigned)(b >> 32)) * (1.0f / (float)P);
        int row = blockIdx.x * BI + tid;
        out_conf[row] = (md > 2.0f) ? 0.0f : expf(-md);
        out_idx[row]  = (float)j;
    }
    if (tid < BI * ROWF) {
        int ilg = tid / ROWF;
        int k   = tid - ilg * ROWF;
        int j   = (int)(unsigned)best[ilg];
        out_mp[(blockIdx.x * BI + ilg) * ROWF + k] = gt[(size_t)j * ROWF + k];
    }
}

extern "C" void kernel_launch(void* const* d_in, const int* in_sizes, int n_in,
                              void* d_out, int out_size)
{
    const float* pred = (const float*)d_in[0];
    const float* gt   = (const float*)d_in[1];
    float* out        = (float*)d_out;

    int N = in_sizes[0] / ROWF;   // 1024
    int M = in_sizes[1] / ROWF;   // 2048

    float* out_mp   = out;
    float* out_conf = out + (size_t)N * ROWF;
    float* out_idx  = out + (size_t)N * ROWF + N;

    static bool attr_set = false;  // host-side only; not in the captured graph
    if (!attr_set) {
        cudaFuncSetAttribute(pointmatcher_kernel,
                             cudaFuncAttributeMaxDynamicSharedMemorySize,
                             SMEM_BYTES);
        attr_set = true;
    }

    pointmatcher_kernel<<<N / BI, THREADS, SMEM_BYTES>>>(
        pred, gt, out_mp, out_conf, out_idx, N, M);
}

// round 8
// speedup vs baseline: 1.1980x; 1.1980x over previous
#include <cuda_runtime.h>
#include <cuda_bf16.h>

// PointMatcher: pred (N=1024,20,2) vs gt (M=2048,20,2)
// dist(i,j) = mean_p ||pred[i,p]-gt[j,p]|| ; argmin over j per i.
// Single kernel. Outputs concatenated in d_out (float32):
//   [0..N*40) matched gt rows | [N*40..N*41) confidence | [N*41..N*42) indices

#define BI      4       // pred rows per block
#define TJ      256     // gt rows per tile
#define HJ      128     // thread handles rows jlane and jlane+HJ
#define P       20
#define ROWF    40      // floats per row
#define ROWP    44      // padded stride: 176B*jlane mod 128 hits 8 distinct banks
#define THREADS 512
#define TILEF   (TJ * ROWP)                  // 11264 floats = 45056 B per buffer
#define SMEM_BYTES (2*TILEF*4 + BI*8)

typedef unsigned long long ull;

__device__ __forceinline__ float fsqrt_approx(float x) {
    float r;
    asm("sqrt.approx.f32 %0, %1;" : "=f"(r) : "f"(x));
    return r;
}
__device__ __forceinline__ void cp_async16(float* dst, const float* src) {
    unsigned sa = (unsigned)__cvta_generic_to_shared(dst);
    asm volatile("cp.async.cg.shared.global [%0], [%1], 16;" :: "r"(sa), "l"(src));
}

__global__ __launch_bounds__(THREADS, 2)
void pointmatcher_kernel(const float* __restrict__ pred,
                         const float* __restrict__ gt,
                         float* __restrict__ out_mp,
                         float* __restrict__ out_conf,
                         float* __restrict__ out_idx,
                         int N, int M)
{
    extern __shared__ float smem[];
    float* buf[2] = { smem, smem + TILEF };
    ull*   best   = (ull*)(smem + 2 * TILEF);

    const int tid   = threadIdx.x;
    const int il    = tid & (BI - 1);    // pred row within block
    const int jlane = tid >> 2;          // 0..127
    const int i     = blockIdx.x * BI + il;

    if (tid < BI) best[tid] = ~0ull;     // visible after first sync in loop

    // NEGATED pred row in registers, packed {x,y} per point as f32x2.
    ull pr[P];
    {
        const float2* p2 = (const float2*)(pred + (size_t)i * ROWF);
        #pragma unroll
        for (int p = 0; p < P; p++) {
            float2 v = p2[p];
            float nx = -v.x, ny = -v.y;
            asm("mov.b64 %0, {%1,%2};" : "=l"(pr[p]) : "f"(nx), "f"(ny));
        }
    }

    // Prefetch tile 0 (TJ*ROWF = 10240 floats = 2560 float4, 5 per thread).
    {
        #pragma unroll
        for (int it = 0; it < 5; it++) {
            int f = tid + it * THREADS;          // float4 index 0..2559
            int row = f / 10, k4 = f - row * 10;
            cp_async16(buf[0] + row * ROWP + k4 * 4, gt + (size_t)f * 4);
        }
        asm volatile("cp.async.commit_group;");
    }

    float minv = 3.402823466e+38f;       // min of SUM over P (mean deferred)
    int   minj = 0;
    const int ntiles = M / TJ;           // 8

    for (int t = 0; t < ntiles; t++) {
        asm volatile("cp.async.wait_group 0;");
        __syncthreads();                 // tile t ready; buf[t^1] free to refill

        if (t + 1 < ntiles) {
            const float* src = gt + (size_t)(t + 1) * TJ * ROWF;
            float* dst = buf[(t + 1) & 1];
            #pragma unroll
            for (int it = 0; it < 5; it++) {
                int f = tid + it * THREADS;
                int row = f / 10, k4 = f - row * 10;
                cp_async16(dst + row * ROWP + k4 * 4, src + (size_t)f * 4);
            }
        }
        asm volatile("cp.async.commit_group;");

        const ull* t0 = (const ull*)(buf[t & 1] + jlane * ROWP);
        const ull* t1 = (const ull*)(buf[t & 1] + (jlane + HJ) * ROWP);
        float sum0 = 0.f, sum1 = 0.f;
        #pragma unroll
        for (int p = 0; p < P; p++) {
            ull d0, d1;
            // packed {dx,dy} = gt + (-pred)
            asm("add.rn.f32x2 %0, %1, %2;" : "=l"(d0) : "l"(t0[p]), "l"(pr[p]));
            asm("add.rn.f32x2 %0, %1, %2;" : "=l"(d1) : "l"(t1[p]), "l"(pr[p]));
            float dx0, dy0, dx1, dy1;
            asm("mov.b64 {%0,%1}, %2;" : "=f"(dx0), "=f"(dy0) : "l"(d0));
            asm("mov.b64 {%0,%1}, %2;" : "=f"(dx1), "=f"(dy1) : "l"(d1));
            sum0 += fsqrt_approx(fmaf(dx0, dx0, dy0 * dy0));
            sum1 += fsqrt_approx(fmaf(dx1, dx1, dy1 * dy1));
        }
        int j0 = t * TJ + jlane;
        int j1 = t * TJ + jlane + HJ;
        if (sum0 < minv) { minv = sum0; minj = j0; }  // ascending j per thread:
        if (sum1 < minv) { minv = sum1; minj = j1; }  // '<' keeps first tie
    }

    // Block argmin: packed (dist_bits, j) -> min == (min dist, then min j).
    ull key = ((ull)__float_as_uint(minv) << 32) | (unsigned)minj;
    atomicMin(&best[il], key);
    __syncthreads();

    if (tid < BI) {
        ull b = best[tid];
        int j = (int)(unsigned)b;
        float md = __uint_as_float((unsigned)(b >> 32)) * (1.0f / (float)P);
        int row  = blockIdx.x * BI + tid;
        out_conf[row] = (md > 2.0f) ? 0.0f : expf(-md);
        out_idx[row]  = (float)j;
    }
    if (tid < BI * ROWF) {
        int ilg = tid / ROWF;
        int k   = tid - ilg * ROWF;
        int j   = (int)(unsigned)best[ilg];
        out_mp[(blockIdx.x * BI + ilg) * ROWF + k] = gt[(size_t)j * ROWF + k];
    }
}

extern "C" void kernel_launch(void* const* d_in, const int* in_sizes, int n_in,
                              void* d_out, int out_size)
{
    const float* pred = (const float*)d_in[0];
    const float* gt   = (const float*)d_in[1];
    float* out        = (float*)d_out;

    int N = in_sizes[0] / ROWF;   // 1024
    int M = in_sizes[1] / ROWF;   // 2048

    float* out_mp   = out;
    float* out_conf = out + (size_t)N * ROWF;
    float* out_idx  = out + (size_t)N * ROWF + N;

    static bool attr_set = false;  // host-side only; not in the captured graph
    if (!attr_set) {
        cudaFuncSetAttribute(pointmatcher_kernel,
                             cudaFuncAttributeMaxDynamicSharedMemorySize,
                             SMEM_BYTES);
        attr_set = true;
    }

    pointmatcher_kernel<<<N / BI, THREADS, SMEM_BYTES>>>(
        pred, gt, out_mp, out_conf, out_idx, N, M);
}

// round 9
// speedup vs baseline: 1.2983x; 1.0837x over previous
#include <cuda_runtime.h>
#include <cuda_bf16.h>

// PointMatcher: pred (N=1024,20,2) vs gt (M=2048,20,2)
// dist(i,j) = mean_p ||pred[i,p]-gt[j,p]|| ; argmin over j per i.
// Split-P scheme: thread pairs (lane^4) each own 10 of the 20 points and 4 gt
// rows per tile; halves combined with one shfl per row.
// Outputs concatenated in d_out (float32):
//   [0..N*40) matched gt rows | [N*40..N*41) confidence | [N*41..N*42) indices

#define BI      4       // pred rows per block
#define TJ      256     // gt rows per tile
#define P       20
#define PH      10      // points per thread (half of P)
#define ROWF    40      // floats per row
#define ROWP    44      // padded stride (16B-aligned rows, conflict-free)
#define THREADS 512
#define TILEF   (TJ * ROWP)                  // 11264 floats = 45056 B per buffer
#define SMEM_BYTES (2*TILEF*4 + BI*8)

typedef unsigned long long ull;

__device__ __forceinline__ float fsqrt_approx(float x) {
    float r;
    asm("sqrt.approx.f32 %0, %1;" : "=f"(r) : "f"(x));
    return r;
}
__device__ __forceinline__ void cp_async16(float* dst, const float* src) {
    unsigned sa = (unsigned)__cvta_generic_to_shared(dst);
    asm volatile("cp.async.cg.shared.global [%0], [%1], 16;" :: "r"(sa), "l"(src));
}
// sqrt((gx-px)^2+(gy-py)^2), pneg = packed {-px,-py}
__device__ __forceinline__ float pd(ull g, ull pneg) {
    ull d;
    asm("add.rn.f32x2 %0, %1, %2;" : "=l"(d) : "l"(g), "l"(pneg));
    float dx, dy;
    asm("mov.b64 {%0,%1}, %2;" : "=f"(dx), "=f"(dy) : "l"(d));
    return fsqrt_approx(fmaf(dx, dx, dy * dy));
}

__global__ __launch_bounds__(THREADS, 2)
void pointmatcher_kernel(const float* __restrict__ pred,
                         const float* __restrict__ gt,
                         float* __restrict__ out_mp,
                         float* __restrict__ out_conf,
                         float* __restrict__ out_idx,
                         int N, int M)
{
    extern __shared__ float smem[];
    float* buf[2] = { smem, smem + TILEF };
    ull*   best   = (ull*)(smem + 2 * TILEF);

    const int tid = threadIdx.x;
    const int il  = tid & 3;             // pred row within block
    const int ph  = (tid >> 2) & 1;      // point-half (shfl partner = lane^4)
    const int jl  = tid >> 3;            // 0..63 -> rows jl+{0,64,128,192}
    const int i   = blockIdx.x * BI + il;

    if (tid < BI) best[tid] = ~0ull;     // visible after first sync in loop

    // This thread's 10 pred points, negated, packed {-x,-y}. 20 regs.
    ull pr[PH];
    {
        const float2* p2 = (const float2*)(pred + (size_t)i * ROWF) + PH * ph;
        #pragma unroll
        for (int p = 0; p < PH; p++) {
            float2 v = p2[p];
            float nx = -v.x, ny = -v.y;
            asm("mov.b64 %0, {%1,%2};" : "=l"(pr[p]) : "f"(nx), "f"(ny));
        }
    }

    // Prefetch tile 0 (2560 float4, 5 per thread).
    {
        #pragma unroll
        for (int it = 0; it < 5; it++) {
            int f = tid + it * THREADS;
            int row = f / 10, k4 = f - row * 10;
            cp_async16(buf[0] + row * ROWP + k4 * 4, gt + (size_t)f * 4);
        }
        asm volatile("cp.async.commit_group;");
    }

    float minv = 3.402823466e+38f;       // min of SUM over P (mean deferred)
    int   minj = 0;
    const int ntiles = M / TJ;           // 8

    for (int t = 0; t < ntiles; t++) {
        asm volatile("cp.async.wait_group 0;");
        __syncthreads();                 // tile t ready; other buf free

        if (t + 1 < ntiles) {
            const float* src = gt + (size_t)(t + 1) * TJ * ROWF;
            float* dst = buf[(t + 1) & 1];
            #pragma unroll
            for (int it = 0; it < 5; it++) {
                int f = tid + it * THREADS;
                int row = f / 10, k4 = f - row * 10;
                cp_async16(dst + row * ROWP + k4 * 4, src + (size_t)f * 4);
            }
        }
        asm volatile("cp.async.commit_group;");

        // Base: row jl, this thread's point-half (floats 20*ph..).
        const float* bp = buf[t & 1] + jl * ROWP + PH * 2 * ph;
        float s0 = 0.f, s1 = 0.f, s2 = 0.f, s3 = 0.f;
        #pragma unroll
        for (int k = 0; k < PH / 2; k++) {        // 2 points per LDS.128
            ulonglong2 g0 = *(const ulonglong2*)(bp + k * 4);
            ulonglong2 g1 = *(const ulonglong2*)(bp +  64 * ROWP + k * 4);
            ulonglong2 g2 = *(const ulonglong2*)(bp + 128 * ROWP + k * 4);
            ulonglong2 g3 = *(const ulonglong2*)(bp + 192 * ROWP + k * 4);
            ull pa = pr[2 * k], pb = pr[2 * k + 1];
            s0 += pd(g0.x, pa); s0 += pd(g0.y, pb);
            s1 += pd(g1.x, pa); s1 += pd(g1.y, pb);
            s2 += pd(g2.x, pa); s2 += pd(g2.y, pb);
            s3 += pd(g3.x, pa); s3 += pd(g3.y, pb);
        }
        // Combine point-halves with the lane^4 partner (same il, jl).
        s0 += __shfl_xor_sync(0xffffffffu, s0, 4);
        s1 += __shfl_xor_sync(0xffffffffu, s1, 4);
        s2 += __shfl_xor_sync(0xffffffffu, s2, 4);
        s3 += __shfl_xor_sync(0xffffffffu, s3, 4);

        int jb = t * TJ + jl;
        if (s0 < minv) { minv = s0; minj = jb;       }  // ascending j order:
        if (s1 < minv) { minv = s1; minj = jb + 64;  }  // strict '<' keeps
        if (s2 < minv) { minv = s2; minj = jb + 128; }  // first occurrence
        if (s3 < minv) { minv = s3; minj = jb + 192; }
    }

    // Block argmin: packed (dist_bits, j); min == (min dist, then min j).
    // ph-partner threads carry identical keys — duplicate atomics are harmless.
    ull key = ((ull)__float_as_uint(minv) << 32) | (unsigned)minj;
    atomicMin(&best[il], key);
    __syncthreads();

    if (tid < BI) {
        ull b = best[tid];
        int j = (int)(unsigned)b;
        float md = __uint_as_float((unsigned)(b >> 32)) * (1.0f / (float)P);
        int row  = blockIdx.x * BI + tid;
        out_conf[row] = (md > 2.0f) ? 0.0f : expf(-md);
        out_idx[row]  = (float)j;
    }
    if (tid < BI * ROWF) {
        int ilg = tid / ROWF;
        int k   = tid - ilg * ROWF;
        int j   = (int)(unsigned)best[ilg];
        out_mp[(blockIdx.x * BI + ilg) * ROWF + k] = gt[(size_t)j * ROWF + k];
    }
}

extern "C" void kernel_launch(void* const* d_in, const int* in_sizes, int n_in,
                              void* d_out, int out_size)
{
    const float* pred = (const float*)d_in[0];
    const float* gt   = (const float*)d_in[1];
    float* out        = (float*)d_out;

    int N = in_sizes[0] / ROWF;   // 1024
    int M = in_sizes[1] / ROWF;   // 2048

    float* out_mp   = out;
    float* out_conf = out + (size_t)N * ROWF;
    float* out_idx  = out + (size_t)N * ROWF + N;

    static bool attr_set = false;  // host-side only; not in the captured graph
    if (!attr_set) {
        cudaFuncSetAttribute(pointmatcher_kernel,
                             cudaFuncAttributeMaxDynamicSharedMemorySize,
                             SMEM_BYTES);
        attr_set = true;
    }

    pointmatcher_kernel<<<N / BI, THREADS, SMEM_BYTES>>>(
        pred, gt, out_mp, out_conf, out_idx, N, M);
}

// round 10
// speedup vs baseline: 1.4299x; 1.1013x over previous
#include <cuda_runtime.h>
#include <cuda_bf16.h>

// PointMatcher: pred (N=1024,20,2) vs gt (M=2048,20,2)
// dist(i,j) = mean_p ||pred[i,p]-gt[j,p]|| ; argmin over j per i.
// Split-P: thread pairs (lane^4) own 10 of 20 points, 4 gt rows each per tile.
// Tiles filled by cp.async.bulk (1 instr per 40KB tile) + mbarrier.
// Outputs concatenated in d_out (float32):
//   [0..N*40) matched gt rows | [N*40..N*41) confidence | [N*41..N*42) indices

#define BI      4       // pred rows per block
#define TJ      256     // gt rows per tile
#define P       20
#define PH      10      // points per thread (half of P)
#define ROWF    40      // floats per row; raw stride (no padding -> contiguous tile)
#define THREADS 512
#define TILEF   (TJ * ROWF)                 // 10240 floats
#define TILEB   (TILEF * 4)                 // 40960 bytes, 16B-multiple
#define SMEM_BYTES (2*TILEB + BI*8 + 2*8)

typedef unsigned long long ull;

__device__ __forceinline__ float fsqrt_approx(float x) {
    float r;
    asm("sqrt.approx.f32 %0, %1;" : "=f"(r) : "f"(x));
    return r;
}
// sqrt((gx-px)^2+(gy-py)^2), pneg = packed {-px,-py}
__device__ __forceinline__ float pd(ull g, ull pneg) {
    ull d;
    asm("add.rn.f32x2 %0, %1, %2;" : "=l"(d) : "l"(g), "l"(pneg));
    float dx, dy;
    asm("mov.b64 {%0,%1}, %2;" : "=f"(dx), "=f"(dy) : "l"(d));
    return fsqrt_approx(fmaf(dx, dx, dy * dy));
}
__device__ __forceinline__ void mbar_init(unsigned mbar, unsigned cnt) {
    asm volatile("mbarrier.init.shared.b64 [%0], %1;" :: "r"(mbar), "r"(cnt) : "memory");
}
__device__ __forceinline__ void mbar_expect_tx(unsigned mbar, unsigned bytes) {
    asm volatile("mbarrier.arrive.expect_tx.shared.b64 _, [%0], %1;"
                 :: "r"(mbar), "r"(bytes) : "memory");
}
__device__ __forceinline__ void bulk_ld(unsigned dst, const void* src,
                                        unsigned bytes, unsigned mbar) {
    asm volatile(
        "cp.async.bulk.shared::cluster.global.mbarrier::complete_tx::bytes "
        "[%0], [%1], %2, [%3];"
        :: "r"(dst), "l"(src), "r"(bytes), "r"(mbar) : "memory");
}
__device__ __forceinline__ void mbar_wait(unsigned mbar, unsigned phase) {
    asm volatile(
        "{\n\t.reg .pred P1;\n\t"
        "W_%=:\n\t"
        "mbarrier.try_wait.parity.acquire.cta.shared::cta.b64 P1, [%0], %1, 0x989680;\n\t"
        "@P1 bra D_%=;\n\t"
        "bra W_%=;\n\t"
        "D_%=:\n\t}"
        :: "r"(mbar), "r"(phase) : "memory");
}

__global__ __launch_bounds__(THREADS, 2)
void pointmatcher_kernel(const float* __restrict__ pred,
                         const float* __restrict__ gt,
                         float* __restrict__ out_mp,
                         float* __restrict__ out_conf,
                         float* __restrict__ out_idx,
                         int N, int M)
{
    extern __shared__ __align__(16) float smem[];
    float* buf[2] = { smem, smem + TILEF };
    ull*   best   = (ull*)(smem + 2 * TILEF);
    unsigned mbar0 = (unsigned)__cvta_generic_to_shared(best + BI);
    unsigned mbar1 = mbar0 + 8;
    unsigned buf_sa[2] = { (unsigned)__cvta_generic_to_shared(buf[0]),
                           (unsigned)__cvta_generic_to_shared(buf[1]) };

    const int tid = threadIdx.x;
    const int il  = tid & 3;             // pred row within block
    const int ph  = (tid >> 2) & 1;      // point-half (shfl partner = lane^4)
    const int jl  = tid >> 3;            // 0..63 -> rows jl+{0,64,128,192}
    const int i   = blockIdx.x * BI + il;

    if (tid < BI) best[tid] = ~0ull;
    if (tid == 0) { mbar_init(mbar0, 1); mbar_init(mbar1, 1); }

    // This thread's 10 pred points, negated, packed {-x,-y}.
    ull pr[PH];
    {
        const float2* p2 = (const float2*)(pred + (size_t)i * ROWF) + PH * ph;
        #pragma unroll
        for (int p = 0; p < PH; p++) {
            float2 v = p2[p];
            float nx = -v.x, ny = -v.y;
            asm("mov.b64 %0, {%1,%2};" : "=l"(pr[p]) : "f"(nx), "f"(ny));
        }
    }

    __syncthreads();                     // mbarrier init + best[] visible
    if (tid == 0) {                      // prefetch tile 0: ONE bulk copy
        mbar_expect_tx(mbar0, TILEB);
        bulk_ld(buf_sa[0], gt, TILEB, mbar0);
    }

    float minv = 3.402823466e+38f;       // min of SUM over P (mean deferred)
    int   minj = 0;
    const int ntiles = M / TJ;           // 8

    for (int t = 0; t < ntiles; t++) {
        unsigned mb = (t & 1) ? mbar1 : mbar0;
        mbar_wait(mb, (t >> 1) & 1);     // tile t landed
        __syncthreads();                 // all threads done reading other buf

        if (tid == 0 && t + 1 < ntiles) {
            unsigned mbn = ((t + 1) & 1) ? mbar1 : mbar0;
            mbar_expect_tx(mbn, TILEB);
            bulk_ld(buf_sa[(t + 1) & 1],
                    gt + (size_t)(t + 1) * TILEF, TILEB, mbn);
        }

        // Base: row jl, this thread's point-half. Stride-40 layout is
        // conflict-free for this pattern (8 addrs, 20 banks apart).
        const float* bp = buf[t & 1] + jl * ROWF + PH * 2 * ph;
        float s0 = 0.f, s1 = 0.f, s2 = 0.f, s3 = 0.f;
        #pragma unroll
        for (int k = 0; k < PH / 2; k++) {        // 2 points per LDS.128
            ulonglong2 g0 = *(const ulonglong2*)(bp + k * 4);
            ulonglong2 g1 = *(const ulonglong2*)(bp +  64 * ROWF + k * 4);
            ulonglong2 g2 = *(const ulonglong2*)(bp + 128 * ROWF + k * 4);
            ulonglong2 g3 = *(const ulonglong2*)(bp + 192 * ROWF + k * 4);
            ull pa = pr[2 * k], pb = pr[2 * k + 1];
            s0 += pd(g0.x, pa); s0 += pd(g0.y, pb);
            s1 += pd(g1.x, pa); s1 += pd(g1.y, pb);
            s2 += pd(g2.x, pa); s2 += pd(g2.y, pb);
            s3 += pd(g3.x, pa); s3 += pd(g3.y, pb);
        }
        // Combine point-halves with the lane^4 partner (same il, jl).
        s0 += __shfl_xor_sync(0xffffffffu, s0, 4);
        s1 += __shfl_xor_sync(0xffffffffu, s1, 4);
        s2 += __shfl_xor_sync(0xffffffffu, s2, 4);
        s3 += __shfl_xor_sync(0xffffffffu, s3, 4);

        int jb = t * TJ + jl;
        if (s0 < minv) { minv = s0; minj = jb;       }  // ascending j order:
        if (s1 < minv) { minv = s1; minj = jb + 64;  }  // strict '<' keeps
        if (s2 < minv) { minv = s2; minj = jb + 128; }  // first occurrence
        if (s3 < minv) { minv = s3; minj = jb + 192; }
    }

    // Block argmin: packed (dist_bits, j); min == (min dist, then min j).
    // ph-partner threads carry identical keys — duplicate atomics harmless.
    ull key = ((ull)__float_as_uint(minv) << 32) | (unsigned)minj;
    atomicMin(&best[il], key);
    __syncthreads();

    if (tid < BI) {
        ull b = best[tid];
        int j = (int)(unsigned)b;
        float md = __uint_as_float((unsigned)(b >> 32)) * (1.0f / (float)P);
        int row  = blockIdx.x * BI + tid;
        out_conf[row] = (md > 2.0f) ? 0.0f : expf(-md);
        out_idx[row]  = (float)j;
    }
    if (tid < BI * ROWF) {
        int ilg = tid / ROWF;
        int k   = tid - ilg * ROWF;
        int j   = (int)(unsigned)best[ilg];
        out_mp[(blockIdx.x * BI + ilg) * ROWF + k] = gt[(size_t)j * ROWF + k];
    }
}

extern "C" void kernel_launch(void* const* d_in, const int* in_sizes, int n_in,
                              void* d_out, int out_size)
{
    const float* pred = (const float*)d_in[0];
    const float* gt   = (const float*)d_in[1];
    float* out        = (float*)d_out;

    int N = in_sizes[0] / ROWF;   // 1024
    int M = in_sizes[1] / ROWF;   // 2048

    float* out_mp   = out;
    float* out_conf = out + (size_t)N * ROWF;
    float* out_idx  = out + (size_t)N * ROWF + N;

    static bool attr_set = false;  // host-side only; not in the captured graph
    if (!attr_set) {
        cudaFuncSetAttribute(pointmatcher_kernel,
                             cudaFuncAttributeMaxDynamicSharedMemorySize,
                             SMEM_BYTES);
        attr_set = true;
    }

    pointmatcher_kernel<<<N / BI, THREADS, SMEM_BYTES>>>(
        pred, gt, out_mp, out_conf, out_idx, N, M);
}